// round 3
// baseline (speedup 1.0000x reference)
#include <cuda_runtime.h>
#include <cuda_fp16.h>
#include <cstdint>

// SparseLinear: out[8192,128] = coo(ids, vals, 8192x8192) @ x[8192,128]
// v3: half-warp-per-entry spmm (LDG.128 gathers, no shfl), packed f32x2 FMA,
//     overflow fixup folded into spmm. Launches: init -> scatter -> spmm.

#define N_ROWS    8192
#define ROW_CAP   512          // mean nnz/row = 256; >15 sigma headroom
#define OVER_CAP  65536

__device__ int     g_is64;
__device__ int     g_count[N_ROWS];
__device__ int     g_over_cnt;
__device__ uint4   g_over[OVER_CAP];            // (row, col, val_bits, 0)
__device__ uint2   g_pack[N_ROWS * ROW_CAP];    // (col, val_bits)  32 MB
__device__ __half2 g_xh[N_ROWS * 64];           // x in fp16, 2 MB (L2-resident)

#define FMA_F32X2(acc, xv, vv) \
    asm("fma.rn.f32x2 %0, %1, %2, %3;" \
        : "=l"(acc) : "l"(xv), "l"(vv), "l"(acc))

// ---------------------------------------------------------------------------
// 1) init: detect id dtype (block 0), zero counters, convert x -> fp16.
// ---------------------------------------------------------------------------
__global__ void init_kernel(const int* __restrict__ ids32,
                            const float* __restrict__ x) {
    int tid    = blockIdx.x * blockDim.x + threadIdx.x;
    int stride = gridDim.x * blockDim.x;

    for (int i = tid; i < N_ROWS; i += stride) g_count[i] = 0;
    if (tid == 0) g_over_cnt = 0;

    // int64 ids with values < 8192 have all-zero odd 32-bit words.
    if (blockIdx.x == 0) {
        __shared__ int s_bad;
        if (threadIdx.x == 0) s_bad = 0;
        __syncthreads();
        int bad = 0;
        for (int i = threadIdx.x; i < 2048; i += blockDim.x)
            if (ids32[2 * i + 1] != 0) bad = 1;
        if (bad) atomicOr(&s_bad, 1);
        __syncthreads();
        if (threadIdx.x == 0) g_is64 = s_bad ? 0 : 1;
    }

    const float4* __restrict__ x4 = reinterpret_cast<const float4*>(x);
    for (int i = tid; i < N_ROWS * 32; i += stride) {
        float4 v = x4[i];
        g_xh[2 * i]     = __floats2half2_rn(v.x, v.y);
        g_xh[2 * i + 1] = __floats2half2_rn(v.z, v.w);
    }
}

// ---------------------------------------------------------------------------
// 2) scatter: single pass, atomic cursor per row, packed 8-byte payload.
// ---------------------------------------------------------------------------
__global__ void scatter_kernel(const int* __restrict__ ids32,
                               const float* __restrict__ vals, int nnz) {
    const int is64 = g_is64;
    int stride = gridDim.x * blockDim.x;
    for (int e = blockIdx.x * blockDim.x + threadIdx.x; e < nnz; e += stride) {
        int row, col;
        if (is64) {
            row = ids32[2 * e];
            col = ids32[2 * (nnz + e)];
        } else {
            row = ids32[e];
            col = ids32[nnz + e];
        }
        float v = vals[e];
        int p = atomicAdd(&g_count[row], 1);
        if (p < ROW_CAP) {
            g_pack[row * ROW_CAP + p] = make_uint2((unsigned)col,
                                                   __float_as_uint(v));
        } else {
            int q = atomicAdd(&g_over_cnt, 1);
            if (q < OVER_CAP)
                g_over[q] = make_uint4((unsigned)row, (unsigned)col,
                                       __float_as_uint(v), 0u);
        }
    }
}

// ---------------------------------------------------------------------------
// 3) spmm: one warp per row, HALF-WARP per entry.
//    Lanes: half = lane>>4 picks entry (base+2u+half), sub = lane&15 owns
//    fp16 cols [8*sub, 8*sub+8) via one LDG.128 (256B per half-warp, L2 hit).
//    Accumulate 8 fp32 per lane as 4 packed f32x2; cross-half shfl reduce at
//    the end. Overflow list (normally empty) handled before the store.
// ---------------------------------------------------------------------------
__global__ void __launch_bounds__(256)
spmm_kernel(float* __restrict__ out) {
    int gwarp = (blockIdx.x * blockDim.x + threadIdx.x) >> 5;
    int lane  = threadIdx.x & 31;
    if (gwarp >= N_ROWS) return;
    int half = lane >> 4;
    int sub  = lane & 15;

    int cnt = g_count[gwarp];
    if (cnt > ROW_CAP) cnt = ROW_CAP;
    const uint2* __restrict__ pk  = g_pack + gwarp * ROW_CAP;
    const uint4* __restrict__ xh4 = reinterpret_cast<const uint4*>(g_xh);

    unsigned long long acc0 = 0ull, acc1 = 0ull, acc2 = 0ull, acc3 = 0ull;

    for (int base = 0; base < cnt; base += 8) {
        #pragma unroll
        for (int u = 0; u < 4; u++) {
            int e = base + 2 * u + half;
            uint2 p = make_uint2(0u, 0u);
            if (e < cnt) p = __ldg(&pk[e]);
            uint4 xr = __ldg(&xh4[p.x * 16 + sub]);

            unsigned long long vv;
            asm("mov.b64 %0, {%1, %1};" : "=l"(vv) : "r"(p.y));

            float2 f0 = __half22float2(*reinterpret_cast<__half2*>(&xr.x));
            float2 f1 = __half22float2(*reinterpret_cast<__half2*>(&xr.y));
            float2 f2 = __half22float2(*reinterpret_cast<__half2*>(&xr.z));
            float2 f3 = __half22float2(*reinterpret_cast<__half2*>(&xr.w));
            unsigned long long x0, x1, x2, x3;
            asm("mov.b64 %0, {%1, %2};" : "=l"(x0) : "f"(f0.x), "f"(f0.y));
            asm("mov.b64 %0, {%1, %2};" : "=l"(x1) : "f"(f1.x), "f"(f1.y));
            asm("mov.b64 %0, {%1, %2};" : "=l"(x2) : "f"(f2.x), "f"(f2.y));
            asm("mov.b64 %0, {%1, %2};" : "=l"(x3) : "f"(f3.x), "f"(f3.y));
            FMA_F32X2(acc0, x0, vv);
            FMA_F32X2(acc1, x1, vv);
            FMA_F32X2(acc2, x2, vv);
            FMA_F32X2(acc3, x3, vv);
        }
    }

    // overflow entries (normally zero): half 0 accumulates matches.
    int nov = g_over_cnt;
    if (nov > OVER_CAP) nov = OVER_CAP;
    for (int q = 0; q < nov; q++) {
        uint4 o = __ldg(&g_over[q]);
        if ((int)o.x == gwarp && half == 0) {
            uint4 xr = __ldg(&xh4[o.y * 16 + sub]);
            unsigned long long vv;
            asm("mov.b64 %0, {%1, %1};" : "=l"(vv) : "r"(o.z));
            float2 f0 = __half22float2(*reinterpret_cast<__half2*>(&xr.x));
            float2 f1 = __half22float2(*reinterpret_cast<__half2*>(&xr.y));
            float2 f2 = __half22float2(*reinterpret_cast<__half2*>(&xr.z));
            float2 f3 = __half22float2(*reinterpret_cast<__half2*>(&xr.w));
            unsigned long long x0, x1, x2, x3;
            asm("mov.b64 %0, {%1, %2};" : "=l"(x0) : "f"(f0.x), "f"(f0.y));
            asm("mov.b64 %0, {%1, %2};" : "=l"(x1) : "f"(f1.x), "f"(f1.y));
            asm("mov.b64 %0, {%1, %2};" : "=l"(x2) : "f"(f2.x), "f"(f2.y));
            asm("mov.b64 %0, {%1, %2};" : "=l"(x3) : "f"(f3.x), "f"(f3.y));
            FMA_F32X2(acc0, x0, vv);
            FMA_F32X2(acc1, x1, vv);
            FMA_F32X2(acc2, x2, vv);
            FMA_F32X2(acc3, x3, vv);
        }
    }

    // unpack, reduce across halves, store (lanes of half 0 write 2 float4).
    float f[8];
    asm("mov.b64 {%0, %1}, %2;" : "=f"(f[0]), "=f"(f[1]) : "l"(acc0));
    asm("mov.b64 {%0, %1}, %2;" : "=f"(f[2]), "=f"(f[3]) : "l"(acc1));
    asm("mov.b64 {%0, %1}, %2;" : "=f"(f[4]), "=f"(f[5]) : "l"(acc2));
    asm("mov.b64 {%0, %1}, %2;" : "=f"(f[6]), "=f"(f[7]) : "l"(acc3));
    #pragma unroll
    for (int k = 0; k < 8; k++)
        f[k] += __shfl_xor_sync(0xffffffffu, f[k], 16);

    if (half == 0) {
        float4* __restrict__ o4 = reinterpret_cast<float4*>(out) + gwarp * 32;
        o4[sub * 2]     = make_float4(f[0], f[1], f[2], f[3]);
        o4[sub * 2 + 1] = make_float4(f[4], f[5], f[6], f[7]);
    }
}

// ---------------------------------------------------------------------------
// Launch
// ---------------------------------------------------------------------------
extern "C" void kernel_launch(void* const* d_in, const int* in_sizes, int n_in,
                              void* d_out, int out_size) {
    const int*   ids32 = (const int*)d_in[0];    // int64 or int32 (detected)
    const float* vals  = (const float*)d_in[1];  // [nnz]
    const float* x     = (const float*)d_in[2];  // [8192, 128] fp32
    float*       out   = (float*)d_out;          // [8192, 128] fp32

    int nnz = in_sizes[1];

    init_kernel<<<592, 256>>>(ids32, x);              // 148 SMs * 4
    scatter_kernel<<<1184, 256>>>(ids32, vals, nnz);  // 148 SMs * 8
    spmm_kernel<<<N_ROWS / 8, 256>>>(out);            // 1 warp / row
}

// round 4
// speedup vs baseline: 1.1827x; 1.1827x over previous
#include <cuda_runtime.h>
#include <cuda_fp16.h>
#include <cstdint>

// SparseLinear: out[8192,128] = coo(ids, vals, 8192x8192) @ x[8192,128]
// v4: v2 spmm shape (shfl-broadcast, max MLP) + 4-byte packed (fp16val|col)
//     entries + vectorized scatter + overflow folded into spmm.
// Launches: init -> scatter -> spmm.

#define N_ROWS    8192
#define ROW_CAP   512          // mean nnz/row = 256; >15 sigma headroom
#define OVER_CAP  65536

__device__ int      g_is64;
__device__ int      g_count[N_ROWS];
__device__ int      g_over_cnt;
__device__ uint2    g_over[OVER_CAP];           // (row, packed)
__device__ unsigned g_pack[N_ROWS * ROW_CAP];   // (fp16 val)<<16 | col   16 MB
__device__ __half2  g_xh[N_ROWS * 64];          // x in fp16, 2 MB (L2-resident)

__device__ __forceinline__ unsigned pack_entry(int col, float v) {
    return (unsigned)col |
           ((unsigned)__half_as_ushort(__float2half_rn(v)) << 16);
}

// ---------------------------------------------------------------------------
// 1) init: detect id dtype (block 0), zero counters, convert x -> fp16.
// ---------------------------------------------------------------------------
__global__ void init_kernel(const int* __restrict__ ids32,
                            const float* __restrict__ x) {
    int tid    = blockIdx.x * blockDim.x + threadIdx.x;
    int stride = gridDim.x * blockDim.x;

    for (int i = tid; i < N_ROWS; i += stride) g_count[i] = 0;
    if (tid == 0) g_over_cnt = 0;

    // int64 ids with values < 8192 have all-zero odd 32-bit words.
    if (blockIdx.x == 0) {
        __shared__ int s_bad;
        if (threadIdx.x == 0) s_bad = 0;
        __syncthreads();
        int bad = 0;
        for (int i = threadIdx.x; i < 2048; i += blockDim.x)
            if (ids32[2 * i + 1] != 0) bad = 1;
        if (bad) atomicOr(&s_bad, 1);
        __syncthreads();
        if (threadIdx.x == 0) g_is64 = s_bad ? 0 : 1;
    }

    const float4* __restrict__ x4 = reinterpret_cast<const float4*>(x);
    for (int i = tid; i < N_ROWS * 32; i += stride) {
        float4 v = x4[i];
        g_xh[2 * i]     = __floats2half2_rn(v.x, v.y);
        g_xh[2 * i + 1] = __floats2half2_rn(v.z, v.w);
    }
}

// ---------------------------------------------------------------------------
// 2) scatter: vectorized id loads, atomic row cursor, 4-byte packed payload.
// ---------------------------------------------------------------------------
__device__ __forceinline__ void scatter_one(int row, int col, float v) {
    int p = atomicAdd(&g_count[row], 1);
    if (p < ROW_CAP) {
        g_pack[row * ROW_CAP + p] = pack_entry(col, v);
    } else {
        int q = atomicAdd(&g_over_cnt, 1);
        if (q < OVER_CAP)
            g_over[q] = make_uint2((unsigned)row, pack_entry(col, v));
    }
}

__global__ void scatter_kernel(const int* __restrict__ ids32,
                               const float* __restrict__ vals, int nnz) {
    int tid    = blockIdx.x * blockDim.x + threadIdx.x;
    int stride = gridDim.x * blockDim.x;

    if (g_is64) {
        // int64: rows at words [0,2nnz) (even=payload), cols at [2nnz,4nnz).
        const int4*   r4 = reinterpret_cast<const int4*>(ids32);
        const int4*   c4 = reinterpret_cast<const int4*>(ids32 + 2 * nnz);
        const float2* v2 = reinterpret_cast<const float2*>(vals);
        int n2 = nnz >> 1;                      // 2 entries per thread
        for (int t = tid; t < n2; t += stride) {
            int4  r = r4[t];
            int4  c = c4[t];
            float2 v = v2[t];
            scatter_one(r.x, c.x, v.x);
            scatter_one(r.z, c.z, v.y);
        }
        if (tid == 0 && (nnz & 1)) {
            int e = nnz - 1;
            scatter_one(ids32[2 * e], ids32[2 * (nnz + e)], vals[e]);
        }
    } else {
        // int32: rows at [0,nnz), cols at [nnz,2nnz).
        const int4*   r4 = reinterpret_cast<const int4*>(ids32);
        const int4*   c4 = reinterpret_cast<const int4*>(ids32 + nnz);
        const float4* v4 = reinterpret_cast<const float4*>(vals);
        int n4 = nnz >> 2;                      // 4 entries per thread
        for (int t = tid; t < n4; t += stride) {
            int4  r = r4[t];
            int4  c = c4[t];
            float4 v = v4[t];
            scatter_one(r.x, c.x, v.x);
            scatter_one(r.y, c.y, v.y);
            scatter_one(r.z, c.z, v.z);
            scatter_one(r.w, c.w, v.w);
        }
        if (tid == 0) {
            for (int e = nnz & ~3; e < nnz; e++)
                scatter_one(ids32[e], ids32[nnz + e], vals[e]);
        }
    }
}

// ---------------------------------------------------------------------------
// 3) spmm: one warp per row. Lane l owns fp16 cols [4l, 4l+4) (one uint2).
//    Packed entries loaded coalesced 32-at-a-time, broadcast via ONE shfl;
//    8 independent 256B gathers in flight per warp (all L2 hits).
// ---------------------------------------------------------------------------
__global__ void __launch_bounds__(256)
spmm_kernel(float* __restrict__ out) {
    int gwarp = (blockIdx.x * blockDim.x + threadIdx.x) >> 5;
    int lane  = threadIdx.x & 31;
    if (gwarp >= N_ROWS) return;

    int cnt = g_count[gwarp];
    if (cnt > ROW_CAP) cnt = ROW_CAP;
    const unsigned* __restrict__ pk = g_pack + gwarp * ROW_CAP;
    const uint2* __restrict__ xh = reinterpret_cast<const uint2*>(g_xh);

    float a0 = 0.f, a1 = 0.f, a2 = 0.f, a3 = 0.f;

    for (int base = 0; base < cnt; base += 32) {
        int idx = base + lane;
        unsigned p = 0u;                       // col 0, val +0.0h -> no-op
        if (idx < cnt) p = __ldg(&pk[idx]);
        int m = cnt - base; if (m > 32) m = 32;
        #pragma unroll 8
        for (int j = 0; j < m; j++) {
            unsigned pj = __shfl_sync(0xffffffffu, p, j);
            float    vj = __half2float(__ushort_as_half((unsigned short)(pj >> 16)));
            uint2 xr = __ldg(&xh[(pj & 0xFFFFu) * 32 + lane]);
            float2 f0 = __half22float2(*reinterpret_cast<__half2*>(&xr.x));
            float2 f1 = __half22float2(*reinterpret_cast<__half2*>(&xr.y));
            a0 += vj * f0.x;
            a1 += vj * f0.y;
            a2 += vj * f1.x;
            a3 += vj * f1.y;
        }
    }

    // overflow entries (normally zero).
    int nov = g_over_cnt;
    if (nov > OVER_CAP) nov = OVER_CAP;
    for (int q = 0; q < nov; q++) {
        uint2 o = __ldg(&g_over[q]);
        if ((int)o.x == gwarp) {
            unsigned pj = o.y;
            float    vj = __half2float(__ushort_as_half((unsigned short)(pj >> 16)));
            uint2 xr = __ldg(&xh[(pj & 0xFFFFu) * 32 + lane]);
            float2 f0 = __half22float2(*reinterpret_cast<__half2*>(&xr.x));
            float2 f1 = __half22float2(*reinterpret_cast<__half2*>(&xr.y));
            a0 += vj * f0.x;
            a1 += vj * f0.y;
            a2 += vj * f1.x;
            a3 += vj * f1.y;
        }
    }

    reinterpret_cast<float4*>(out)[gwarp * 32 + lane] =
        make_float4(a0, a1, a2, a3);
}

// ---------------------------------------------------------------------------
// Launch
// ---------------------------------------------------------------------------
extern "C" void kernel_launch(void* const* d_in, const int* in_sizes, int n_in,
                              void* d_out, int out_size) {
    const int*   ids32 = (const int*)d_in[0];    // int64 or int32 (detected)
    const float* vals  = (const float*)d_in[1];  // [nnz]
    const float* x     = (const float*)d_in[2];  // [8192, 128] fp32
    float*       out   = (float*)d_out;          // [8192, 128] fp32

    int nnz = in_sizes[1];

    init_kernel<<<592, 256>>>(ids32, x);              // 148 SMs * 4
    scatter_kernel<<<1184, 256>>>(ids32, vals, nnz);  // 148 SMs * 8
    spmm_kernel<<<N_ROWS / 8, 256>>>(out);            // 1 warp / row
}

// round 5
// speedup vs baseline: 1.2878x; 1.0889x over previous
#include <cuda_runtime.h>
#include <cuda_fp16.h>
#include <cstdint>

// SparseLinear: out[8192,128] = coo(ids, vals, 8192x8192) @ x[8192,128]
// v5: smem-tiled chunked SpMM.
//   - bucket entries by (col-chunk of 256, row): 32*8192 buckets, CAP 32
//   - spmm: 128 blocks x 1024 thr; block owns 64 rows, loops 32 chunks;
//     x chunk (64KB fp16) cp.async double-buffered into smem; gathers via LDS.
// Launches: init -> scatter -> spmm.

#define N_ROWS      8192
#define N_CHUNK     32
#define CHUNK_COLS  256
#define CHUNK_BYTES (CHUNK_COLS * 128 * 2)   // 65536: 256 x-rows of 256B fp16
#define CAP         32                        // mean 8 entries/bucket
#define OVER_CAP    65536
#define R_PER_BLK   64
#define N_BLOCKS    (N_ROWS / R_PER_BLK)      // 128

__device__ int      g_is64;
__device__ int      g_bcnt[N_CHUNK * N_ROWS];            // 1 MB
__device__ int      g_over_cnt;
__device__ uint2    g_over[OVER_CAP];                    // (row, val<<16|col)
__device__ unsigned g_bpack[N_CHUNK * N_ROWS * CAP];     // 32 MB: val<<16|colOff
__device__ __half2  g_xh[N_ROWS * 64];                   // x fp16, 2 MB

// ---------------------------------------------------------------------------
// 1) init: detect id dtype, zero bucket counters, convert x -> fp16.
// ---------------------------------------------------------------------------
__global__ void init_kernel(const int* __restrict__ ids32,
                            const float* __restrict__ x) {
    int tid    = blockIdx.x * blockDim.x + threadIdx.x;
    int stride = gridDim.x * blockDim.x;

    for (int i = tid; i < N_CHUNK * N_ROWS; i += stride) g_bcnt[i] = 0;
    if (tid == 0) g_over_cnt = 0;

    // int64 ids with values < 8192 have all-zero odd 32-bit words.
    if (blockIdx.x == 0) {
        __shared__ int s_bad;
        if (threadIdx.x == 0) s_bad = 0;
        __syncthreads();
        int bad = 0;
        for (int i = threadIdx.x; i < 2048; i += blockDim.x)
            if (ids32[2 * i + 1] != 0) bad = 1;
        if (bad) atomicOr(&s_bad, 1);
        __syncthreads();
        if (threadIdx.x == 0) g_is64 = s_bad ? 0 : 1;
    }

    const float4* __restrict__ x4 = reinterpret_cast<const float4*>(x);
    for (int i = tid; i < N_ROWS * 32; i += stride) {
        float4 v = x4[i];
        g_xh[2 * i]     = __floats2half2_rn(v.x, v.y);
        g_xh[2 * i + 1] = __floats2half2_rn(v.z, v.w);
    }
}

// ---------------------------------------------------------------------------
// 2) scatter into (chunk,row) buckets; 4-byte packed (fp16 val | colOff).
// ---------------------------------------------------------------------------
__device__ __forceinline__ void scatter_one(int row, int col, float v) {
    unsigned vh   = (unsigned)__half_as_ushort(__float2half_rn(v));
    int      chnk = col >> 8;
    int      b    = chnk * N_ROWS + row;
    int p = atomicAdd(&g_bcnt[b], 1);
    if (p < CAP) {
        g_bpack[b * CAP + p] = (vh << 16) | (unsigned)(col & 0xFF);
    } else {
        int q = atomicAdd(&g_over_cnt, 1);
        if (q < OVER_CAP)
            g_over[q] = make_uint2((unsigned)row, (vh << 16) | (unsigned)col);
    }
}

__global__ void scatter_kernel(const int* __restrict__ ids32,
                               const float* __restrict__ vals, int nnz) {
    const int is64 = g_is64;
    int stride = gridDim.x * blockDim.x;
    for (int e = blockIdx.x * blockDim.x + threadIdx.x; e < nnz; e += stride) {
        int row, col;
        if (is64) {
            row = ids32[2 * e];
            col = ids32[2 * (nnz + e)];
        } else {
            row = ids32[e];
            col = ids32[nnz + e];
        }
        scatter_one(row, col, vals[e]);
    }
}

// ---------------------------------------------------------------------------
// 3) spmm: block = 64 rows, loop over 32 col-chunks; x chunk in smem
//    (cp.async double-buffered). Warp w handles rows r0+w, r0+w+32.
//    Lane l owns cols [4l,4l+4) -> one 8B LDS per entry, conflict-free.
// ---------------------------------------------------------------------------
__device__ __forceinline__ void copy_chunk_async(unsigned char* dst, int c) {
    const unsigned char* src =
        reinterpret_cast<const unsigned char*>(g_xh) + (size_t)c * CHUNK_BYTES;
    int t = threadIdx.x;
    #pragma unroll
    for (int i = 0; i < CHUNK_BYTES / 16 / 1024; i++) {   // 4 iters
        int off = (t + i * 1024) * 16;
        unsigned saddr = (unsigned)__cvta_generic_to_shared(dst + off);
        asm volatile("cp.async.cg.shared.global [%0], [%1], 16;\n"
                     :: "r"(saddr), "l"(src + off));
    }
}

__global__ void __launch_bounds__(1024, 1)
spmm_kernel(float* __restrict__ out) {
    extern __shared__ unsigned char s_x[];   // 2 * 64KB
    int r0   = blockIdx.x * R_PER_BLK;
    int w    = threadIdx.x >> 5;
    int lane = threadIdx.x & 31;

    float4 acc0 = make_float4(0.f, 0.f, 0.f, 0.f);
    float4 acc1 = make_float4(0.f, 0.f, 0.f, 0.f);

    copy_chunk_async(s_x, 0);
    asm volatile("cp.async.commit_group;\n");

    for (int c = 0; c < N_CHUNK; c++) {
        if (c + 1 < N_CHUNK) {
            copy_chunk_async(s_x + ((c + 1) & 1) * CHUNK_BYTES, c + 1);
            asm volatile("cp.async.commit_group;\n");
            asm volatile("cp.async.wait_group 1;\n");
        } else {
            asm volatile("cp.async.wait_group 0;\n");
        }
        __syncthreads();

        const unsigned char* buf = s_x + (c & 1) * CHUNK_BYTES;

        #pragma unroll
        for (int k = 0; k < 2; k++) {
            int r   = r0 + w + 32 * k;
            int b   = c * N_ROWS + r;
            int cnt = __ldg(&g_bcnt[b]);
            if (cnt > CAP) cnt = CAP;
            unsigned p = 0u;
            if (lane < cnt) p = __ldg(&g_bpack[b * CAP + lane]);
            #pragma unroll 4
            for (int j = 0; j < cnt; j++) {
                unsigned pj = __shfl_sync(0xffffffffu, p, j);
                float    vj = __half2float(__ushort_as_half(
                                  (unsigned short)(pj >> 16)));
                uint2 xr = *reinterpret_cast<const uint2*>(
                               buf + (pj & 0xFFu) * 256 + lane * 8);
                float2 f0 = __half22float2(*reinterpret_cast<__half2*>(&xr.x));
                float2 f1 = __half22float2(*reinterpret_cast<__half2*>(&xr.y));
                if (k == 0) {
                    acc0.x += vj * f0.x;  acc0.y += vj * f0.y;
                    acc0.z += vj * f1.x;  acc0.w += vj * f1.y;
                } else {
                    acc1.x += vj * f0.x;  acc1.y += vj * f0.y;
                    acc1.z += vj * f1.x;  acc1.w += vj * f1.y;
                }
            }
        }
        __syncthreads();
    }

    // overflow entries (normally zero).
    int nov = g_over_cnt;
    if (nov > OVER_CAP) nov = OVER_CAP;
    const uint2* __restrict__ xg = reinterpret_cast<const uint2*>(g_xh);
    for (int q = 0; q < nov; q++) {
        uint2 o  = __ldg(&g_over[q]);
        int   dr = (int)o.x - r0;
        if (dr >= 0 && dr < R_PER_BLK && (dr & 31) == w) {
            float    vj  = __half2float(__ushort_as_half(
                              (unsigned short)(o.y >> 16)));
            unsigned col = o.y & 0xFFFFu;
            uint2 xr = __ldg(&xg[col * 32 + lane]);
            float2 f0 = __half22float2(*reinterpret_cast<__half2*>(&xr.x));
            float2 f1 = __half22float2(*reinterpret_cast<__half2*>(&xr.y));
            if (dr < 32) {
                acc0.x += vj * f0.x;  acc0.y += vj * f0.y;
                acc0.z += vj * f1.x;  acc0.w += vj * f1.y;
            } else {
                acc1.x += vj * f0.x;  acc1.y += vj * f0.y;
                acc1.z += vj * f1.x;  acc1.w += vj * f1.y;
            }
        }
    }

    float4* __restrict__ o4 = reinterpret_cast<float4*>(out);
    o4[(r0 + w) * 32 + lane]      = acc0;
    o4[(r0 + w + 32) * 32 + lane] = acc1;
}

// ---------------------------------------------------------------------------
// Launch
// ---------------------------------------------------------------------------
extern "C" void kernel_launch(void* const* d_in, const int* in_sizes, int n_in,
                              void* d_out, int out_size) {
    const int*   ids32 = (const int*)d_in[0];    // int64 or int32 (detected)
    const float* vals  = (const float*)d_in[1];  // [nnz]
    const float* x     = (const float*)d_in[2];  // [8192, 128] fp32
    float*       out   = (float*)d_out;          // [8192, 128] fp32

    int nnz = in_sizes[1];

    cudaFuncSetAttribute(spmm_kernel,
                         cudaFuncAttributeMaxDynamicSharedMemorySize,
                         2 * CHUNK_BYTES);

    init_kernel<<<592, 256>>>(ids32, x);
    scatter_kernel<<<1184, 256>>>(ids32, vals, nnz);
    spmm_kernel<<<N_BLOCKS, 1024, 2 * CHUNK_BYTES>>>(out);
}